// round 2
// baseline (speedup 1.0000x reference)
#include <cuda_runtime.h>
#include <math.h>
#include <stdint.h>

// ---------------- problem constants ----------------
#define BSZ   2
#define LSEQ  512
#define DMODEL 1024
#define DINNER 2048
#define DSTATE 64
#define KCONV 4
#define MROWS (BSZ*LSEQ)     // 1024
#define NXP   129            // 2*DSTATE + 1
#define KCH   8              // split-K chunks for x-proj
#define KSZ   (DINNER/KCH)   // 256
#define OUT_ELEMS (MROWS*DMODEL)   // 1048576 floats of `out`

// ---------------- device scratch ----------------
__device__ float g_xz  [MROWS * 2 * DINNER];
__device__ float g_xs  [MROWS * DINNER];
__device__ float g_xpp [KCH * MROWS * NXP];
__device__ float g_Bm  [MROWS * DSTATE];
__device__ float g_Cm  [MROWS * DSTATE];
__device__ float g_dtr [MROWS];
__device__ float g_dt  [MROWS * DINNER];
__device__ float g_y   [MROWS * DINNER];

// ---------------- tf32 helpers ----------------
__device__ __forceinline__ uint2 split_tf32(float x) {
    float hi; asm("cvt.rna.tf32.f32 %0, %1;" : "=f"(hi) : "f"(x));
    float lo = x - hi;
    float lo2; asm("cvt.rna.tf32.f32 %0, %1;" : "=f"(lo2) : "f"(lo));
    uint2 r; r.x = __float_as_uint(hi); r.y = __float_as_uint(lo2);
    return r;
}

__device__ __forceinline__ void mma_tf32(float4& d,
    uint32_t a0, uint32_t a1, uint32_t a2, uint32_t a3,
    uint32_t b0, uint32_t b1)
{
    asm volatile(
        "mma.sync.aligned.m16n8k8.row.col.f32.tf32.tf32.f32 "
        "{%0,%1,%2,%3}, {%4,%5,%6,%7}, {%8,%9}, {%0,%1,%2,%3};"
        : "+f"(d.x), "+f"(d.y), "+f"(d.z), "+f"(d.w)
        : "r"(a0), "r"(a1), "r"(a2), "r"(a3), "r"(b0), "r"(b1));
}

// ---------------- tf32x3 GEMM: C = A[M,K] @ B[K,N] ----------------
// grid (N/128, M/128, ksplit). ksplit>1 => atomicAdd into pre-zeroed C.
// block 256 threads = 8 warps (2 x 4), warp tile 64x32, BK=16.
__global__ __launch_bounds__(256) void gemm_tf32x3(
    const float* __restrict__ A, const float* __restrict__ B,
    float* __restrict__ C, int M, int N, int K, int ksplit)
{
    __shared__ uint2 sA[16][130];
    __shared__ uint2 sB[16][130];

    const int tid  = threadIdx.x;
    const int lane = tid & 31;
    const int warp = tid >> 5;
    const int wm   = warp >> 2;     // 0..1
    const int wn   = warp & 3;      // 0..3
    const int gid  = lane >> 2;     // 0..7
    const int tig  = lane & 3;      // 0..3

    const int kchunk = K / ksplit;
    const int kbeg   = blockIdx.z * kchunk;

    const float* Ab = A + (size_t)blockIdx.y * 128 * K + kbeg;
    const float* Bb = B + (size_t)kbeg * N + blockIdx.x * 128;

    float4 acc[4][4];
#pragma unroll
    for (int i = 0; i < 4; i++)
#pragma unroll
        for (int j = 0; j < 4; j++) acc[i][j] = make_float4(0.f, 0.f, 0.f, 0.f);

    for (int k0 = 0; k0 < kchunk; k0 += 16) {
#pragma unroll
        for (int i = 0; i < 2; i++) {
            int idx = tid * 2 + i;
            // A stage: row = idx>>2 (0..127), k = (idx&3)*4 .. +3
            int ar = idx >> 2, ak = (idx & 3) * 4;
            float4 v = *(const float4*)(Ab + (size_t)ar * K + k0 + ak);
            sA[ak + 0][ar] = split_tf32(v.x);
            sA[ak + 1][ar] = split_tf32(v.y);
            sA[ak + 2][ar] = split_tf32(v.z);
            sA[ak + 3][ar] = split_tf32(v.w);
            // B stage: k = idx>>5 (0..15), col = (idx&31)*4 .. +3
            int bk = idx >> 5, bc = (idx & 31) * 4;
            float4 w = *(const float4*)(Bb + (size_t)(k0 + bk) * N + bc);
            sB[bk][bc + 0] = split_tf32(w.x);
            sB[bk][bc + 1] = split_tf32(w.y);
            sB[bk][bc + 2] = split_tf32(w.z);
            sB[bk][bc + 3] = split_tf32(w.w);
        }
        __syncthreads();

#pragma unroll
        for (int ks = 0; ks < 16; ks += 8) {
            uint2 bq[4][2];
#pragma unroll
            for (int nf = 0; nf < 4; nf++) {
                int c = wn * 32 + nf * 8 + gid;
                bq[nf][0] = sB[ks + tig][c];
                bq[nf][1] = sB[ks + tig + 4][c];
            }
#pragma unroll
            for (int mf = 0; mf < 4; mf++) {
                int r = wm * 64 + mf * 16 + gid;
                uint2 a0 = sA[ks + tig][r];
                uint2 a1 = sA[ks + tig][r + 8];
                uint2 a2 = sA[ks + tig + 4][r];
                uint2 a3 = sA[ks + tig + 4][r + 8];
#pragma unroll
                for (int nf = 0; nf < 4; nf++) {
                    // hi*hi + hi*lo + lo*hi
                    mma_tf32(acc[mf][nf], a0.x, a1.x, a2.x, a3.x, bq[nf][0].x, bq[nf][1].x);
                    mma_tf32(acc[mf][nf], a0.x, a1.x, a2.x, a3.x, bq[nf][0].y, bq[nf][1].y);
                    mma_tf32(acc[mf][nf], a0.y, a1.y, a2.y, a3.y, bq[nf][0].x, bq[nf][1].x);
                }
            }
        }
        __syncthreads();
    }

    // epilogue
#pragma unroll
    for (int mf = 0; mf < 4; mf++) {
#pragma unroll
        for (int nf = 0; nf < 4; nf++) {
            int r = blockIdx.y * 128 + wm * 64 + mf * 16 + gid;
            int c = blockIdx.x * 128 + wn * 32 + nf * 8 + tig * 2;
            float4 v = acc[mf][nf];
            if (ksplit == 1) {
                *(float2*)(C + (size_t)r * N + c)       = make_float2(v.x, v.y);
                *(float2*)(C + (size_t)(r + 8) * N + c) = make_float2(v.z, v.w);
            } else {
                atomicAdd(C + (size_t)r * N + c,           v.x);
                atomicAdd(C + (size_t)r * N + c + 1,       v.y);
                atomicAdd(C + (size_t)(r + 8) * N + c,     v.z);
                atomicAdd(C + (size_t)(r + 8) * N + c + 1, v.w);
            }
        }
    }
}

// ---------------- depthwise causal conv (K=4) + bias + SiLU ----------------
__global__ void conv_silu_kernel(const float* __restrict__ conv_w,
                                 const float* __restrict__ conv_b)
{
    const int m = blockIdx.x;
    const int b = m / LSEQ;
    const int l = m % LSEQ;
    for (int c = threadIdx.x; c < DINNER; c += blockDim.x) {
        float s = conv_b[c];
#pragma unroll
        for (int k = 0; k < KCONV; k++) {
            int ls = l - (KCONV - 1) + k;
            if (ls >= 0)
                s += g_xz[(size_t)(b * LSEQ + ls) * (2 * DINNER) + c] * conv_w[c * KCONV + k];
        }
        float sil = s / (1.f + __expf(-s));
        g_xs[(size_t)m * DINNER + c] = sil;
    }
}

// ---------------- x-proj split-K partials ----------------
__global__ __launch_bounds__(160) void xp_partial_kernel(const float* __restrict__ W)
{
    __shared__ float s[16][KSZ];
    const int m0 = blockIdx.x * 16;
    const int k0 = blockIdx.y * KSZ;
    const int tid = threadIdx.x;

    for (int idx = tid; idx < 16 * KSZ; idx += blockDim.x) {
        int r = idx / KSZ, k = idx % KSZ;
        s[r][k] = g_xs[(size_t)(m0 + r) * DINNER + k0 + k];
    }
    __syncthreads();

    if (tid < NXP) {
        float acc[16];
#pragma unroll
        for (int r = 0; r < 16; r++) acc[r] = 0.f;
        for (int k = 0; k < KSZ; k++) {
            float w = W[(size_t)(k0 + k) * NXP + tid];
#pragma unroll
            for (int r = 0; r < 16; r++) acc[r] += s[r][k] * w;
        }
#pragma unroll
        for (int r = 0; r < 16; r++)
            g_xpp[(size_t)(blockIdx.y * MROWS + m0 + r) * NXP + tid] = acc[r];
    }
}

__global__ __launch_bounds__(160) void xp_reduce_kernel()
{
    const int m = blockIdx.x;
    const int n = threadIdx.x;
    if (n >= NXP) return;
    float sum = 0.f;
#pragma unroll
    for (int kc = 0; kc < KCH; kc++)
        sum += g_xpp[(size_t)(kc * MROWS + m) * NXP + n];
    if (n < DSTATE)            g_Bm[m * DSTATE + n] = sum;
    else if (n < 2 * DSTATE)   g_Cm[m * DSTATE + (n - DSTATE)] = sum;
    else                       g_dtr[m] = sum;
}

// ---------------- dt = softplus(dt_raw * dt_w + dt_b) ----------------
__global__ void dt_kernel(const float* __restrict__ dt_w,
                          const float* __restrict__ dt_b)
{
    const int m = blockIdx.x;
    const float dr = g_dtr[m];
    for (int c = threadIdx.x; c < DINNER; c += blockDim.x) {
        float v = dr * dt_w[c] + dt_b[c];
        float sp = (v > 20.f) ? v : log1pf(expf(v));
        g_dt[(size_t)m * DINNER + c] = sp;
    }
}

// ---------------- selective scan: block = (b, 8 d-channels), smem-staged ----
__global__ __launch_bounds__(256) void scan_kernel(
    const float* __restrict__ A_log, const float* __restrict__ Dp,
    float* __restrict__ state_out)
{
    __shared__ float sB[2][64], sC[2][64], sdt[2][8], sxs[2][8], sz[2][8];

    const int tid  = threadIdx.x;
    const int warp = tid >> 5;
    const int lane = tid & 31;
    const int b  = blockIdx.x >> 8;           // 0..1
    const int d0 = (blockIdx.x & 255) * 8;
    const int d  = d0 + warp;

    const float a0 = -__expf(A_log[d * DSTATE + lane]);
    const float a1 = -__expf(A_log[d * DSTATE + lane + 32]);
    const float Dd = Dp[d];

    // stage t into buffer p
    auto stage = [&](int t, int p) {
        const int m = b * LSEQ + t;
        if (tid < 64)        sB[p][tid]        = g_Bm[m * DSTATE + tid];
        else if (tid < 128)  sC[p][tid - 64]   = g_Cm[m * DSTATE + tid - 64];
        else if (tid < 136)  sdt[p][tid - 128] = g_dt[(size_t)m * DINNER + d0 + tid - 128];
        else if (tid < 144)  sxs[p][tid - 136] = g_xs[(size_t)m * DINNER + d0 + tid - 136];
        else if (tid < 152)  sz[p][tid - 144]  = g_xz[(size_t)m * (2 * DINNER) + DINNER + d0 + tid - 144];
    };

    stage(0, 0);
    float s0 = 0.f, s1 = 0.f;
    int p = 0;
    for (int t = 0; t < LSEQ; ++t) {
        __syncthreads();
        if (t + 1 < LSEQ) stage(t + 1, p ^ 1);

        const float dtv = sdt[p][warp];
        const float xv  = sxs[p][warp];
        const float zv  = sz[p][warp];
        const float b0  = sB[p][lane];
        const float b1  = sB[p][lane + 32];
        const float c0  = sC[p][lane];
        const float c1  = sC[p][lane + 32];

        const float dx = dtv * xv;
        s0 = __expf(dtv * a0) * s0 + dx * b0;
        s1 = __expf(dtv * a1) * s1 + dx * b1;

        float acc = s0 * c0 + s1 * c1;
#pragma unroll
        for (int o = 16; o; o >>= 1) acc += __shfl_xor_sync(0xffffffffu, acc, o);

        if (lane == 0) {
            const int m = b * LSEQ + t;
            float y = acc + Dd * xv;
            float sg = zv / (1.f + __expf(-zv));
            g_y[(size_t)m * DINNER + d] = y * sg;
        }
        p ^= 1;
    }
    state_out[(size_t)(b * DINNER + d) * DSTATE + lane]      = s0;
    state_out[(size_t)(b * DINNER + d) * DSTATE + lane + 32] = s1;
}

// ---------------- launch ----------------
extern "C" void kernel_launch(void* const* d_in, const int* in_sizes, int n_in,
                              void* d_out, int out_size)
{
    const float* x          = (const float*)d_in[0];
    const float* in_proj_w  = (const float*)d_in[1];
    const float* conv_w     = (const float*)d_in[2];
    const float* conv_b     = (const float*)d_in[3];
    const float* x_proj_w   = (const float*)d_in[4];
    const float* dt_w       = (const float*)d_in[5];
    const float* dt_b       = (const float*)d_in[6];
    const float* A_log      = (const float*)d_in[7];
    const float* Dp         = (const float*)d_in[8];
    const float* out_proj_w = (const float*)d_in[9];
    float* out = (float*)d_out;

    void* p;
    cudaGetSymbolAddress(&p, g_xz); float* p_xz = (float*)p;
    cudaGetSymbolAddress(&p, g_y);  float* p_y  = (float*)p;

    // zero the split-K output of GEMM3
    cudaMemsetAsync(out, 0, (size_t)OUT_ELEMS * sizeof(float));

    // 1) xz = x @ in_proj_w   (1024 x 4096 x 1024), tensor-core tf32x3
    gemm_tf32x3<<<dim3(2 * DINNER / 128, MROWS / 128, 1), 256>>>(
        x, in_proj_w, p_xz, MROWS, 2 * DINNER, DMODEL, 1);

    // 2) depthwise causal conv + SiLU
    conv_silu_kernel<<<MROWS, 256>>>(conv_w, conv_b);

    // 3) xp = xs @ x_proj_w (split-K) -> Bm, Cm, dt_raw
    xp_partial_kernel<<<dim3(MROWS / 16, KCH), 160>>>(x_proj_w);
    xp_reduce_kernel<<<MROWS, 160>>>();

    // 4) dt = softplus(dt_raw * dt_w + dt_b)
    dt_kernel<<<MROWS, 256>>>(dt_w, dt_b);

    // 5) selective scan -> g_y, final state -> d_out tail
    scan_kernel<<<512, 256>>>(A_log, Dp, out + OUT_ELEMS);

    // 6) out = y @ out_proj_w (1024 x 1024 x 2048), tensor-core tf32x3, split-K4
    gemm_tf32x3<<<dim3(DMODEL / 128, MROWS / 128, 4), 256>>>(
        p_y, out_proj_w, out, MROWS, DMODEL, DINNER, 4);
}

// round 4
// speedup vs baseline: 1.2991x; 1.2991x over previous
#include <cuda_runtime.h>
#include <cuda_fp16.h>
#include <math.h>
#include <stdint.h>

// ---------------- problem constants ----------------
#define BSZ   2
#define LSEQ  512
#define DMODEL 1024
#define DINNER 2048
#define DSTATE 64
#define KCONV 4
#define MROWS (BSZ*LSEQ)     // 1024
#define NXP   129
#define KCH   8
#define KSZ   (DINNER/KCH)
#define OUT_ELEMS (MROWS*DMODEL)

// ---------------- device scratch ----------------
__device__ __align__(16) float g_xz  [MROWS * 2 * DINNER];
__device__ __align__(16) float g_xs  [MROWS * DINNER];
__device__ __align__(16) float g_xpp [KCH * MROWS * NXP];
__device__ __align__(16) float g_Bm  [MROWS * DSTATE];
__device__ __align__(16) float g_Cm  [MROWS * DSTATE];
__device__ __align__(16) float g_dtr [MROWS];
__device__ __align__(16) float g_y   [MROWS * DINNER];

// ================= fp16x3 GEMM config =================
#define BM 128
#define BN 128
#define BK 32
#define APITCH 40                      // halfs per A row (32 + 8 pad) = 80B
#define BPITCH 40                      // halfs per B^T row = 80B
#define ASTAGE (BM*APITCH)             // 5120 halfs
#define BSTAGE (BN*BPITCH)             // 5120 halfs
#define STAGEH (2*(ASTAGE+BSTAGE))     // 20480 halfs / stage (Ah,Al,Bh,Bl)
#define GSMEM  (2*STAGEH*2)            // 81920 bytes (double buffer)

__device__ __forceinline__ void mma16816(float4& d,
    uint32_t a0, uint32_t a1, uint32_t a2, uint32_t a3,
    uint32_t b0, uint32_t b1)
{
    asm volatile(
        "mma.sync.aligned.m16n8k16.row.col.f32.f16.f16.f32 "
        "{%0,%1,%2,%3}, {%4,%5,%6,%7}, {%8,%9}, {%0,%1,%2,%3};"
        : "+f"(d.x), "+f"(d.y), "+f"(d.z), "+f"(d.w)
        : "r"(a0), "r"(a1), "r"(a2), "r"(a3), "r"(b0), "r"(b1));
}

__device__ __forceinline__ void cvt_hl(float x, float y, uint32_t& hi, uint32_t& lo)
{
    __half2 h = __floats2half2_rn(x, y);
    float2 hf = __half22float2(h);
    __half2 l = __floats2half2_rn(x - hf.x, y - hf.y);
    hi = *(uint32_t*)&h;
    lo = *(uint32_t*)&l;
}

// C[M,N] = A[M,K] @ B[K,N], fp32 in/out, fp16x3 tensor-core compute.
// ksplit>1 -> atomicAdd into pre-zeroed C.
__global__ __launch_bounds__(256) void gemm_f16x3(
    const float* __restrict__ A, const float* __restrict__ B,
    float* __restrict__ C, int M, int N, int K, int ksplit)
{
    extern __shared__ __half sm[];
    const int tid  = threadIdx.x;
    const int lane = tid & 31, warp = tid >> 5;
    const int gid  = lane >> 2, tig = lane & 3;
    const int wm   = warp >> 2, wn = warp & 3;
    const int m0 = blockIdx.y * BM, n0 = blockIdx.x * BN;
    const int kchunk = K / ksplit;
    const int kbeg   = blockIdx.z * kchunk;
    const int NCH    = kchunk / BK;

    // staging coordinates
    const int am   = tid >> 1;          // A row this thread stages
    const int ak   = (tid & 1) * 16;    // A k-offset
    const int bn   = tid & 127;         // B column this thread stages
    const int bg   = (tid >> 7) * 16;   // B k-offset
    const int brot = (bn >> 3) & 7;     // store rotation to avoid bank conflicts

    const float* Aug = A + (size_t)(m0 + am) * K + kbeg + ak;
    const float* Bug = B + (size_t)(kbeg + bg) * N + n0 + bn;

    float ar[16], br[16];

    auto gload = [&](int koff) {
#pragma unroll
        for (int j = 0; j < 4; ++j) {
            float4 v = *(const float4*)(Aug + koff + j * 4);
            ar[j*4+0] = v.x; ar[j*4+1] = v.y; ar[j*4+2] = v.z; ar[j*4+3] = v.w;
        }
#pragma unroll
        for (int j = 0; j < 16; ++j)
            br[j] = Bug[(size_t)(koff + j) * N];
    };

    auto sstore = [&](int p) {
        __half* base = sm + p * STAGEH;
        __half* sAh = base;
        __half* sAl = base + ASTAGE;
        __half* sBh = base + 2 * ASTAGE;
        __half* sBl = sBh + BSTAGE;
#pragma unroll
        for (int j = 0; j < 8; ++j) {
            uint32_t hi, lo;
            cvt_hl(ar[j*2], ar[j*2+1], hi, lo);
            int off = am * APITCH + ak + j * 2;
            *(uint32_t*)(sAh + off) = hi;
            *(uint32_t*)(sAl + off) = lo;
        }
#pragma unroll
        for (int i = 0; i < 8; ++i) {
            int jj = (i + brot) & 7;
            uint32_t hi, lo;
            cvt_hl(br[jj*2], br[jj*2+1], hi, lo);
            int off = bn * BPITCH + bg + jj * 2;   // B stored transposed: [n][k]
            *(uint32_t*)(sBh + off) = hi;
            *(uint32_t*)(sBl + off) = lo;
        }
    };

    float4 acc[4][4];
#pragma unroll
    for (int i = 0; i < 4; i++)
#pragma unroll
        for (int j = 0; j < 4; j++) acc[i][j] = make_float4(0.f, 0.f, 0.f, 0.f);

    gload(0);
    sstore(0);
    __syncthreads();

    for (int c = 0; c < NCH; ++c) {
        const int p = c & 1;
        if (c + 1 < NCH) gload((c + 1) * BK);

        const __half* base = sm + p * STAGEH;
        const __half* sAh = base;
        const __half* sAl = base + ASTAGE;
        const __half* sBh = base + 2 * ASTAGE;
        const __half* sBl = sBh + BSTAGE;

#pragma unroll
        for (int ks = 0; ks < 2; ++ks) {
            const int kb = ks * 16 + tig * 2;
            uint32_t bh[4][2], bl[4][2];
#pragma unroll
            for (int nf = 0; nf < 4; ++nf) {
                const __half* q  = sBh + (wn * 32 + nf * 8 + gid) * BPITCH + kb;
                const __half* ql = sBl + (wn * 32 + nf * 8 + gid) * BPITCH + kb;
                bh[nf][0] = *(const uint32_t*)q;
                bh[nf][1] = *(const uint32_t*)(q + 8);
                bl[nf][0] = *(const uint32_t*)ql;
                bl[nf][1] = *(const uint32_t*)(ql + 8);
            }
#pragma unroll
            for (int mf = 0; mf < 4; ++mf) {
                const __half* qa = sAh + (wm * 64 + mf * 16 + gid) * APITCH + kb;
                const __half* qb = sAl + (wm * 64 + mf * 16 + gid) * APITCH + kb;
                uint32_t ah0 = *(const uint32_t*)qa;
                uint32_t ah1 = *(const uint32_t*)(qa + 8 * APITCH);
                uint32_t ah2 = *(const uint32_t*)(qa + 8);
                uint32_t ah3 = *(const uint32_t*)(qa + 8 * APITCH + 8);
                uint32_t al0 = *(const uint32_t*)qb;
                uint32_t al1 = *(const uint32_t*)(qb + 8 * APITCH);
                uint32_t al2 = *(const uint32_t*)(qb + 8);
                uint32_t al3 = *(const uint32_t*)(qb + 8 * APITCH + 8);
#pragma unroll
                for (int nf = 0; nf < 4; ++nf) {
                    mma16816(acc[mf][nf], ah0, ah1, ah2, ah3, bh[nf][0], bh[nf][1]);
                    mma16816(acc[mf][nf], ah0, ah1, ah2, ah3, bl[nf][0], bl[nf][1]);
                    mma16816(acc[mf][nf], al0, al1, al2, al3, bh[nf][0], bh[nf][1]);
                }
            }
        }
        if (c + 1 < NCH) sstore(p ^ 1);
        __syncthreads();
    }

#pragma unroll
    for (int mf = 0; mf < 4; ++mf)
#pragma unroll
        for (int nf = 0; nf < 4; ++nf) {
            int r  = m0 + wm * 64 + mf * 16 + gid;
            int cc = n0 + wn * 32 + nf * 8 + tig * 2;
            float4 v = acc[mf][nf];
            if (ksplit == 1) {
                *(float2*)(C + (size_t)r * N + cc)       = make_float2(v.x, v.y);
                *(float2*)(C + (size_t)(r + 8) * N + cc) = make_float2(v.z, v.w);
            } else {
                atomicAdd(C + (size_t)r * N + cc,           v.x);
                atomicAdd(C + (size_t)r * N + cc + 1,       v.y);
                atomicAdd(C + (size_t)(r + 8) * N + cc,     v.z);
                atomicAdd(C + (size_t)(r + 8) * N + cc + 1, v.w);
            }
        }
}

// ---------------- depthwise causal conv (K=4) + bias + SiLU ----------------
__global__ void conv_silu_kernel(const float* __restrict__ conv_w,
                                 const float* __restrict__ conv_b)
{
    const int m = blockIdx.x;
    const int b = m / LSEQ;
    const int l = m % LSEQ;
    for (int c = threadIdx.x; c < DINNER; c += blockDim.x) {
        float s = conv_b[c];
#pragma unroll
        for (int k = 0; k < KCONV; k++) {
            int ls = l - (KCONV - 1) + k;
            if (ls >= 0)
                s += g_xz[(size_t)(b * LSEQ + ls) * (2 * DINNER) + c] * conv_w[c * KCONV + k];
        }
        float sil = s / (1.f + __expf(-s));
        g_xs[(size_t)m * DINNER + c] = sil;
    }
}

// ---------------- x-proj split-K partials ----------------
__global__ __launch_bounds__(160) void xp_partial_kernel(const float* __restrict__ W)
{
    __shared__ float s[16][KSZ];
    const int m0 = blockIdx.x * 16;
    const int k0 = blockIdx.y * KSZ;
    const int tid = threadIdx.x;

    for (int idx = tid; idx < 16 * KSZ; idx += blockDim.x) {
        int r = idx / KSZ, k = idx % KSZ;
        s[r][k] = g_xs[(size_t)(m0 + r) * DINNER + k0 + k];
    }
    __syncthreads();

    if (tid < NXP) {
        float acc[16];
#pragma unroll
        for (int r = 0; r < 16; r++) acc[r] = 0.f;
        for (int k = 0; k < KSZ; k++) {
            float w = W[(size_t)(k0 + k) * NXP + tid];
#pragma unroll
            for (int r = 0; r < 16; r++) acc[r] += s[r][k] * w;
        }
#pragma unroll
        for (int r = 0; r < 16; r++)
            g_xpp[(size_t)(blockIdx.y * MROWS + m0 + r) * NXP + tid] = acc[r];
    }
}

__global__ __launch_bounds__(160) void xp_reduce_kernel()
{
    const int m = blockIdx.x;
    const int n = threadIdx.x;
    if (n >= NXP) return;
    float sum = 0.f;
#pragma unroll
    for (int kc = 0; kc < KCH; kc++)
        sum += g_xpp[(size_t)(kc * MROWS + m) * NXP + n];
    if (n < DSTATE)            g_Bm[m * DSTATE + n] = sum;
    else if (n < 2 * DSTATE)   g_Cm[m * DSTATE + (n - DSTATE)] = sum;
    else                       g_dtr[m] = sum;
}

// ---------------- selective scan (dt softplus fused into staging) ----------
__global__ __launch_bounds__(256) void scan_kernel(
    const float* __restrict__ A_log, const float* __restrict__ Dp,
    const float* __restrict__ dt_w, const float* __restrict__ dt_b,
    float* __restrict__ state_out)
{
    __shared__ float sB[2][64], sC[2][64], sdt[2][8], sxs[2][8], sz[2][8];

    const int tid  = threadIdx.x;
    const int warp = tid >> 5;
    const int lane = tid & 31;
    const int b  = blockIdx.x >> 8;
    const int d0 = (blockIdx.x & 255) * 8;
    const int d  = d0 + warp;

    const float a0 = -__expf(A_log[d * DSTATE + lane]);
    const float a1 = -__expf(A_log[d * DSTATE + lane + 32]);
    const float Dd = Dp[d];

    float dw = 0.f, db = 0.f;
    if (tid >= 128 && tid < 136) {
        dw = dt_w[d0 + tid - 128];
        db = dt_b[d0 + tid - 128];
    }

    auto stage = [&](int t, int p) {
        const int m = b * LSEQ + t;
        if (tid < 64)        sB[p][tid]      = g_Bm[m * DSTATE + tid];
        else if (tid < 128)  sC[p][tid - 64] = g_Cm[m * DSTATE + tid - 64];
        else if (tid < 136) {
            float v = g_dtr[m] * dw + db;
            sdt[p][tid - 128] = (v > 20.f) ? v : log1pf(__expf(v));
        }
        else if (tid < 144)  sxs[p][tid - 136] = g_xs[(size_t)m * DINNER + d0 + tid - 136];
        else if (tid < 152)  sz[p][tid - 144]  = g_xz[(size_t)m * (2 * DINNER) + DINNER + d0 + tid - 144];
    };

    stage(0, 0);
    float s0 = 0.f, s1 = 0.f;
    int p = 0;
    for (int t = 0; t < LSEQ; ++t) {
        __syncthreads();
        if (t + 1 < LSEQ) stage(t + 1, p ^ 1);

        const float dtv = sdt[p][warp];
        const float xv  = sxs[p][warp];
        const float zv  = sz[p][warp];
        const float b0  = sB[p][lane];
        const float b1  = sB[p][lane + 32];
        const float c0  = sC[p][lane];
        const float c1  = sC[p][lane + 32];

        const float dx = dtv * xv;
        s0 = __expf(dtv * a0) * s0 + dx * b0;
        s1 = __expf(dtv * a1) * s1 + dx * b1;

        float acc = s0 * c0 + s1 * c1;
#pragma unroll
        for (int o = 16; o; o >>= 1) acc += __shfl_xor_sync(0xffffffffu, acc, o);

        if (lane == 0) {
            const int m = b * LSEQ + t;
            float y = acc + Dd * xv;
            float sg = zv / (1.f + __expf(-zv));
            g_y[(size_t)m * DINNER + d] = y * sg;
        }
        p ^= 1;
    }
    state_out[(size_t)(b * DINNER + d) * DSTATE + lane]      = s0;
    state_out[(size_t)(b * DINNER + d) * DSTATE + lane + 32] = s1;
}

// ---------------- launch ----------------
extern "C" void kernel_launch(void* const* d_in, const int* in_sizes, int n_in,
                              void* d_out, int out_size)
{
    const float* x          = (const float*)d_in[0];
    const float* in_proj_w  = (const float*)d_in[1];
    const float* conv_w     = (const float*)d_in[2];
    const float* conv_b     = (const float*)d_in[3];
    const float* x_proj_w   = (const float*)d_in[4];
    const float* dt_w       = (const float*)d_in[5];
    const float* dt_b       = (const float*)d_in[6];
    const float* A_log      = (const float*)d_in[7];
    const float* Dp         = (const float*)d_in[8];
    const float* out_proj_w = (const float*)d_in[9];
    float* out = (float*)d_out;

    void* p;
    cudaGetSymbolAddress(&p, g_xz); float* p_xz = (float*)p;
    cudaGetSymbolAddress(&p, g_y);  float* p_y  = (float*)p;

    cudaFuncSetAttribute(gemm_f16x3, cudaFuncAttributeMaxDynamicSharedMemorySize, GSMEM);

    // zero C for split-K GEMM3
    cudaMemsetAsync(out, 0, (size_t)OUT_ELEMS * sizeof(float));

    // 1) xz = x @ in_proj_w  (M=1024, N=4096, K=1024)
    gemm_f16x3<<<dim3(2 * DINNER / BN, MROWS / BM, 1), 256, GSMEM>>>(
        x, in_proj_w, p_xz, MROWS, 2 * DINNER, DMODEL, 1);

    // 2) depthwise causal conv + SiLU
    conv_silu_kernel<<<MROWS, 256>>>(conv_w, conv_b);

    // 3) xp = xs @ x_proj_w (split-K fp32) -> Bm, Cm, dt_raw
    xp_partial_kernel<<<dim3(MROWS / 16, KCH), 160>>>(x_proj_w);
    xp_reduce_kernel<<<MROWS, 160>>>();

    // 4) selective scan (softplus fused) -> g_y, final state -> d_out tail
    scan_kernel<<<512, 256>>>(A_log, Dp, dt_w, dt_b, out + OUT_ELEMS);

    // 5) out = y @ out_proj_w (M=1024, N=1024, K=2048), split-K=4
    gemm_f16x3<<<dim3(DMODEL / BN, MROWS / BM, 4), 256, GSMEM>>>(
        p_y, out_proj_w, out, MROWS, DMODEL, DINNER, 4);
}